// round 1
// baseline (speedup 1.0000x reference)
#include <cuda_runtime.h>
#include <cuda_bf16.h>
#include <cstdint>

// Problem constants
#define NROWS 4096
#define DIM   256
#define NBLK  32            // 4096 / 128
// 10 * log2(e): exp(10*d - 10) = exp2(d*K - K)
#define LOG2E10 14.42695040888963f

// ---------------- device scratch (no allocations allowed) ----------------
__device__ __align__(16) __nv_bfloat16 g_Zn[2ull * NROWS * DIM]; // [view][row][dim], view0 = z_j, view1 = z_i
__device__ float g_pos[NROWS];                                   // cross-view positive dot (normalized)
__device__ float g_rowsum[2 * NBLK * NROWS];                     // [view][colblock][row]
__device__ float g_blocksum[32];

__device__ __forceinline__ float fast_ex2(float x) {
    float y;
    asm("ex2.approx.ftz.f32 %0, %1;" : "=f"(y) : "f"(x));
    return y;
}

// ---------------- kernel 1: normalize rows, compute pos --------------------
// One warp per row-index i: processes z_i[i] and z_j[i] together.
__global__ void normalize_kernel(const float* __restrict__ zi, const float* __restrict__ zj) {
    int warp = threadIdx.x >> 5;
    int lane = threadIdx.x & 31;
    int row  = blockIdx.x * 8 + warp;

    const float4* zi4 = reinterpret_cast<const float4*>(zi + (size_t)row * DIM);
    const float4* zj4 = reinterpret_cast<const float4*>(zj + (size_t)row * DIM);
    float4 a0 = zi4[lane * 2], a1 = zi4[lane * 2 + 1];
    float4 b0 = zj4[lane * 2], b1 = zj4[lane * 2 + 1];

    float si = a0.x*a0.x + a0.y*a0.y + a0.z*a0.z + a0.w*a0.w
             + a1.x*a1.x + a1.y*a1.y + a1.z*a1.z + a1.w*a1.w;
    float sj = b0.x*b0.x + b0.y*b0.y + b0.z*b0.z + b0.w*b0.w
             + b1.x*b1.x + b1.y*b1.y + b1.z*b1.z + b1.w*b1.w;
    float dd = a0.x*b0.x + a0.y*b0.y + a0.z*b0.z + a0.w*b0.w
             + a1.x*b1.x + a1.y*b1.y + a1.z*b1.z + a1.w*b1.w;

    #pragma unroll
    for (int o = 16; o; o >>= 1) {
        si += __shfl_xor_sync(0xffffffffu, si, o);
        sj += __shfl_xor_sync(0xffffffffu, sj, o);
        dd += __shfl_xor_sync(0xffffffffu, dd, o);
    }
    float rsI = rsqrtf(si);
    float rsJ = rsqrtf(sj);

    // view 0 = z_j normalized, view 1 = z_i normalized (bf16, packed 16B stores)
    {
        __nv_bfloat162 p0 = __floats2bfloat162_rn(b0.x * rsJ, b0.y * rsJ);
        __nv_bfloat162 p1 = __floats2bfloat162_rn(b0.z * rsJ, b0.w * rsJ);
        __nv_bfloat162 p2 = __floats2bfloat162_rn(b1.x * rsJ, b1.y * rsJ);
        __nv_bfloat162 p3 = __floats2bfloat162_rn(b1.z * rsJ, b1.w * rsJ);
        uint4 u;
        u.x = *reinterpret_cast<unsigned*>(&p0);
        u.y = *reinterpret_cast<unsigned*>(&p1);
        u.z = *reinterpret_cast<unsigned*>(&p2);
        u.w = *reinterpret_cast<unsigned*>(&p3);
        reinterpret_cast<uint4*>(g_Zn)[((size_t)row * DIM + lane * 8) / 8] = u;
    }
    {
        __nv_bfloat162 p0 = __floats2bfloat162_rn(a0.x * rsI, a0.y * rsI);
        __nv_bfloat162 p1 = __floats2bfloat162_rn(a0.z * rsI, a0.w * rsI);
        __nv_bfloat162 p2 = __floats2bfloat162_rn(a1.x * rsI, a1.y * rsI);
        __nv_bfloat162 p3 = __floats2bfloat162_rn(a1.z * rsI, a1.w * rsI);
        uint4 u;
        u.x = *reinterpret_cast<unsigned*>(&p0);
        u.y = *reinterpret_cast<unsigned*>(&p1);
        u.z = *reinterpret_cast<unsigned*>(&p2);
        u.w = *reinterpret_cast<unsigned*>(&p3);
        reinterpret_cast<uint4*>(g_Zn)[((size_t)NROWS * DIM + (size_t)row * DIM + lane * 8) / 8] = u;
    }
    if (lane == 0) g_pos[row] = dd * rsI * rsJ;
}

// ---------------- kernel 2: Gram tile + fused exp row-sum ------------------
// 128x128 output tile, K=256, BK=32, bf16 mma.sync m16n8k16.
// Smem layout: [128 rows][40 bf16] (pad 8 => 80B row stride, conflict-free
// for both cp.async stores and direct LDS fragment loads).
__global__ __launch_bounds__(256) void gram_kernel() {
    const int v  = blockIdx.z;
    const int bm = blockIdx.y;
    const int bn = blockIdx.x;

    __shared__ __align__(16) __nv_bfloat16 As[2][128 * 40];
    __shared__ __align__(16) __nv_bfloat16 Bs[2][128 * 40];
    __shared__ float s_rowsum[128];

    const int tid  = threadIdx.x;
    const int lane = tid & 31;
    const int w    = tid >> 5;
    const int warpM = w >> 2;        // 0..1
    const int warpN = w & 3;         // 0..3
    const int gid  = lane >> 2;      // 0..7
    const int tig  = lane & 3;       // 0..3

    if (tid < 128) s_rowsum[tid] = 0.0f;

    const __nv_bfloat16* Zv = g_Zn + (size_t)v * NROWS * DIM;
    const __nv_bfloat16* Ag = Zv + (size_t)bm * 128 * DIM;
    const __nv_bfloat16* Bg = Zv + (size_t)bn * 128 * DIM;

    float d[4][4][4];
    #pragma unroll
    for (int mt = 0; mt < 4; ++mt)
        #pragma unroll
        for (int nt = 0; nt < 4; ++nt)
            #pragma unroll
            for (int x = 0; x < 4; ++x) d[mt][nt][x] = 0.0f;

    // async copy of one 128x32 stage for A and B
    #define LOAD_STAGE(buf, k0)                                                         \
        do {                                                                            \
            _Pragma("unroll")                                                           \
            for (int p = 0; p < 2; ++p) {                                               \
                int c  = tid + p * 256;                                                 \
                int r  = c >> 2;                                                        \
                int cp = c & 3;                                                         \
                const void* ga = Ag + r * DIM + (k0) + cp * 8;                          \
                unsigned sa = (unsigned)__cvta_generic_to_shared(&As[buf][r * 40 + cp * 8]); \
                asm volatile("cp.async.cg.shared.global [%0], [%1], 16;\n" ::           \
                             "r"(sa), "l"(ga));                                         \
                const void* gb = Bg + r * DIM + (k0) + cp * 8;                          \
                unsigned sb = (unsigned)__cvta_generic_to_shared(&Bs[buf][r * 40 + cp * 8]); \
                asm volatile("cp.async.cg.shared.global [%0], [%1], 16;\n" ::           \
                             "r"(sb), "l"(gb));                                         \
            }                                                                           \
            asm volatile("cp.async.commit_group;\n");                                   \
        } while (0)

    LOAD_STAGE(0, 0);

    for (int kt = 0; kt < 8; ++kt) {
        if (kt < 7) {
            LOAD_STAGE((kt + 1) & 1, (kt + 1) * 32);
            asm volatile("cp.async.wait_group 1;\n");
        } else {
            asm volatile("cp.async.wait_group 0;\n");
        }
        __syncthreads();

        const unsigned* A32 = reinterpret_cast<const unsigned*>(As[kt & 1]);
        const unsigned* B32 = reinterpret_cast<const unsigned*>(Bs[kt & 1]);

        #pragma unroll
        for (int ks = 0; ks < 2; ++ks) {
            const int c0 = ks * 8 + tig;   // uint32 column within 40-bf16 (=20 u32) row
            unsigned a[4][4], b[4][2];
            #pragma unroll
            for (int mt = 0; mt < 4; ++mt) {
                int r0 = (warpM * 64 + mt * 16 + gid) * 20;
                a[mt][0] = A32[r0 + c0];
                a[mt][1] = A32[r0 + 160 + c0];      // +8 rows
                a[mt][2] = A32[r0 + c0 + 4];        // +8 in k
                a[mt][3] = A32[r0 + 160 + c0 + 4];
            }
            #pragma unroll
            for (int nt = 0; nt < 4; ++nt) {
                int r0 = (warpN * 32 + nt * 8 + gid) * 20;
                b[nt][0] = B32[r0 + c0];
                b[nt][1] = B32[r0 + c0 + 4];
            }
            #pragma unroll
            for (int mt = 0; mt < 4; ++mt)
                #pragma unroll
                for (int nt = 0; nt < 4; ++nt)
                    asm volatile(
                        "mma.sync.aligned.m16n8k16.row.col.f32.bf16.bf16.f32 "
                        "{%0,%1,%2,%3}, {%4,%5,%6,%7}, {%8,%9}, {%0,%1,%2,%3};\n"
                        : "+f"(d[mt][nt][0]), "+f"(d[mt][nt][1]),
                          "+f"(d[mt][nt][2]), "+f"(d[mt][nt][3])
                        : "r"(a[mt][0]), "r"(a[mt][1]), "r"(a[mt][2]), "r"(a[mt][3]),
                          "r"(b[nt][0]), "r"(b[nt][1]));
        }
        __syncthreads();
    }

    // epilogue: exp(10*d - 10) and per-row sums (diagonal included; fixed up later)
    #pragma unroll
    for (int mt = 0; mt < 4; ++mt) {
        float s1 = 0.0f, s2 = 0.0f;
        #pragma unroll
        for (int nt = 0; nt < 4; ++nt) {
            s1 += fast_ex2(fmaf(d[mt][nt][0], LOG2E10, -LOG2E10));
            s1 += fast_ex2(fmaf(d[mt][nt][1], LOG2E10, -LOG2E10));
            s2 += fast_ex2(fmaf(d[mt][nt][2], LOG2E10, -LOG2E10));
            s2 += fast_ex2(fmaf(d[mt][nt][3], LOG2E10, -LOG2E10));
        }
        s1 += __shfl_xor_sync(0xffffffffu, s1, 1);
        s1 += __shfl_xor_sync(0xffffffffu, s1, 2);
        s2 += __shfl_xor_sync(0xffffffffu, s2, 1);
        s2 += __shfl_xor_sync(0xffffffffu, s2, 2);
        if (tig == 0) {
            atomicAdd(&s_rowsum[warpM * 64 + mt * 16 + gid],     s1);
            atomicAdd(&s_rowsum[warpM * 64 + mt * 16 + gid + 8], s2);
        }
    }
    __syncthreads();
    if (tid < 128)
        g_rowsum[((size_t)v * NBLK + bn) * NROWS + bm * 128 + tid] = s_rowsum[tid];
}

// ---------------- kernel 3a: per-row lse - pos, block partials -------------
__global__ void finalize_kernel() {
    int tid = threadIdx.x;
    int gid = blockIdx.x * 256 + tid;         // 0..8191
    int v = gid >> 12;
    int i = gid & (NROWS - 1);

    float s = 0.0f;
    #pragma unroll
    for (int b = 0; b < NBLK; ++b)
        s += g_rowsum[((size_t)v * NBLK + b) * NROWS + i];

    float p10 = 10.0f * g_pos[i];
    // remove (approx) self term exp(0)=1, add positive
    float A = s - 1.0f + __expf(p10 - 10.0f);
    float term = 10.0f + logf(A) - p10;       // lse - pos

    __shared__ float red[256];
    red[tid] = term;
    __syncthreads();
    #pragma unroll
    for (int o = 128; o; o >>= 1) {
        if (tid < o) red[tid] += red[tid + o];
        __syncthreads();
    }
    if (tid == 0) g_blocksum[blockIdx.x] = red[0];
}

// ---------------- kernel 3b: final scalar ----------------------------------
__global__ void finalize2_kernel(float* __restrict__ out) {
    int lane = threadIdx.x;
    float s = g_blocksum[lane];
    #pragma unroll
    for (int o = 16; o; o >>= 1) s += __shfl_xor_sync(0xffffffffu, s, o);
    if (lane == 0) out[0] = s / 8192.0f;
}

// ---------------- launch ---------------------------------------------------
extern "C" void kernel_launch(void* const* d_in, const int* in_sizes, int n_in,
                              void* d_out, int out_size) {
    const float* zi = (const float*)d_in[0];   // z_i
    const float* zj = (const float*)d_in[1];   // z_j

    normalize_kernel<<<NROWS / 8, 256>>>(zi, zj);
    gram_kernel<<<dim3(NBLK, NBLK, 2), 256>>>();
    finalize_kernel<<<32, 256>>>();
    finalize2_kernel<<<1, 32>>>((float*)d_out);
}

// round 2
// speedup vs baseline: 1.7144x; 1.7144x over previous
#include <cuda_runtime.h>
#include <cuda_bf16.h>
#include <cstdint>

// Problem constants
#define NROWS 4096
#define DIM   256
#define NBLK  32            // 4096 / 128
#define NTRI  528           // NBLK*(NBLK+1)/2
// 10 * log2(e): exp(10*d - 10) = exp2(d*K - K)
#define LOG2E10 14.42695040888963f

// ---------------- device scratch (no allocations allowed) ----------------
__device__ __align__(16) __nv_bfloat16 g_Zn[2ull * NROWS * DIM]; // [view][row][dim], view0 = z_j, view1 = z_i
__device__ float g_pos[NROWS];                                   // cross-view positive dot (normalized)
__device__ float g_rowsum[2 * NBLK * NROWS];                     // [view][colblock][row]
__device__ float g_blocksum[32];

__device__ __forceinline__ float fast_ex2(float x) {
    float y;
    asm("ex2.approx.ftz.f32 %0, %1;" : "=f"(y) : "f"(x));
    return y;
}

// ---------------- kernel 1: normalize rows, compute pos --------------------
__global__ void normalize_kernel(const float* __restrict__ zi, const float* __restrict__ zj) {
    int warp = threadIdx.x >> 5;
    int lane = threadIdx.x & 31;
    int row  = blockIdx.x * 8 + warp;

    const float4* zi4 = reinterpret_cast<const float4*>(zi + (size_t)row * DIM);
    const float4* zj4 = reinterpret_cast<const float4*>(zj + (size_t)row * DIM);
    float4 a0 = zi4[lane * 2], a1 = zi4[lane * 2 + 1];
    float4 b0 = zj4[lane * 2], b1 = zj4[lane * 2 + 1];

    float si = a0.x*a0.x + a0.y*a0.y + a0.z*a0.z + a0.w*a0.w
             + a1.x*a1.x + a1.y*a1.y + a1.z*a1.z + a1.w*a1.w;
    float sj = b0.x*b0.x + b0.y*b0.y + b0.z*b0.z + b0.w*b0.w
             + b1.x*b1.x + b1.y*b1.y + b1.z*b1.z + b1.w*b1.w;
    float dd = a0.x*b0.x + a0.y*b0.y + a0.z*b0.z + a0.w*b0.w
             + a1.x*b1.x + a1.y*b1.y + a1.z*b1.z + a1.w*b1.w;

    #pragma unroll
    for (int o = 16; o; o >>= 1) {
        si += __shfl_xor_sync(0xffffffffu, si, o);
        sj += __shfl_xor_sync(0xffffffffu, sj, o);
        dd += __shfl_xor_sync(0xffffffffu, dd, o);
    }
    float rsI = rsqrtf(si);
    float rsJ = rsqrtf(sj);

    {
        __nv_bfloat162 p0 = __floats2bfloat162_rn(b0.x * rsJ, b0.y * rsJ);
        __nv_bfloat162 p1 = __floats2bfloat162_rn(b0.z * rsJ, b0.w * rsJ);
        __nv_bfloat162 p2 = __floats2bfloat162_rn(b1.x * rsJ, b1.y * rsJ);
        __nv_bfloat162 p3 = __floats2bfloat162_rn(b1.z * rsJ, b1.w * rsJ);
        uint4 u;
        u.x = *reinterpret_cast<unsigned*>(&p0);
        u.y = *reinterpret_cast<unsigned*>(&p1);
        u.z = *reinterpret_cast<unsigned*>(&p2);
        u.w = *reinterpret_cast<unsigned*>(&p3);
        reinterpret_cast<uint4*>(g_Zn)[((size_t)row * DIM + lane * 8) / 8] = u;
    }
    {
        __nv_bfloat162 p0 = __floats2bfloat162_rn(a0.x * rsI, a0.y * rsI);
        __nv_bfloat162 p1 = __floats2bfloat162_rn(a0.z * rsI, a0.w * rsI);
        __nv_bfloat162 p2 = __floats2bfloat162_rn(a1.x * rsI, a1.y * rsI);
        __nv_bfloat162 p3 = __floats2bfloat162_rn(a1.z * rsI, a1.w * rsI);
        uint4 u;
        u.x = *reinterpret_cast<unsigned*>(&p0);
        u.y = *reinterpret_cast<unsigned*>(&p1);
        u.z = *reinterpret_cast<unsigned*>(&p2);
        u.w = *reinterpret_cast<unsigned*>(&p3);
        reinterpret_cast<uint4*>(g_Zn)[((size_t)NROWS * DIM + (size_t)row * DIM + lane * 8) / 8] = u;
    }
    if (lane == 0) g_pos[row] = dd * rsI * rsJ;
}

// ---------------- kernel 2: triangular Gram + fused exp row/col sums -------
// Only upper-triangular 128x128 blocks (bm<=bn) per view. Off-diagonal tiles
// contribute row sums (rows of bm-block) AND column sums (rows of bn-block
// by symmetry). Each g_rowsum slot written exactly once.
__global__ __launch_bounds__(256, 2) void gram_kernel() {
    const int v = blockIdx.y;

    // triangular decode of blockIdx.x -> (bm, bn), bm <= bn
    int t = blockIdx.x, bm = 0, rem = NBLK;
    while (t >= rem) { t -= rem; ++bm; --rem; }
    const int bn = bm + t;
    const bool diag = (bm == bn);

    __shared__ __align__(16) __nv_bfloat16 As[2][128 * 40];
    __shared__ __align__(16) __nv_bfloat16 Bs[2][128 * 40];
    __shared__ float s_rowsum[128];
    __shared__ float s_colsum[128];

    const int tid  = threadIdx.x;
    const int lane = tid & 31;
    const int w    = tid >> 5;
    const int warpM = w >> 2;        // 0..1
    const int warpN = w & 3;         // 0..3
    const int gid  = lane >> 2;      // 0..7
    const int tig  = lane & 3;       // 0..3

    if (tid < 128) { s_rowsum[tid] = 0.0f; s_colsum[tid] = 0.0f; }

    const __nv_bfloat16* Zv = g_Zn + (size_t)v * NROWS * DIM;
    const __nv_bfloat16* Ag = Zv + (size_t)bm * 128 * DIM;
    const __nv_bfloat16* Bg = Zv + (size_t)bn * 128 * DIM;

    float d[4][4][4];
    #pragma unroll
    for (int mt = 0; mt < 4; ++mt)
        #pragma unroll
        for (int nt = 0; nt < 4; ++nt)
            #pragma unroll
            for (int x = 0; x < 4; ++x) d[mt][nt][x] = 0.0f;

    // per-lane ldmatrix offsets (bf16 units *2 => bytes), 40-bf16 row stride
    const unsigned aLaneOff = (unsigned)(((lane & 15) * 40 + (lane >> 4) * 8) * 2);
    const unsigned bLaneOff = (unsigned)(((((lane >> 4) * 8) + (lane & 7)) * 40 + ((lane >> 3) & 1) * 8) * 2);
    const unsigned sA0 = (unsigned)__cvta_generic_to_shared(&As[0][0]);
    const unsigned sA1 = (unsigned)__cvta_generic_to_shared(&As[1][0]);
    const unsigned sB0 = (unsigned)__cvta_generic_to_shared(&Bs[0][0]);
    const unsigned sB1 = (unsigned)__cvta_generic_to_shared(&Bs[1][0]);

    #define LOAD_STAGE(buf, k0)                                                         \
        do {                                                                            \
            _Pragma("unroll")                                                           \
            for (int p = 0; p < 2; ++p) {                                               \
                int c  = tid + p * 256;                                                 \
                int r  = c >> 2;                                                        \
                int cp = c & 3;                                                         \
                const void* ga = Ag + r * DIM + (k0) + cp * 8;                          \
                unsigned sa = (unsigned)__cvta_generic_to_shared(&As[buf][r * 40 + cp * 8]); \
                asm volatile("cp.async.cg.shared.global [%0], [%1], 16;\n" ::           \
                             "r"(sa), "l"(ga));                                         \
                const void* gb = Bg + r * DIM + (k0) + cp * 8;                          \
                unsigned sb = (unsigned)__cvta_generic_to_shared(&Bs[buf][r * 40 + cp * 8]); \
                asm volatile("cp.async.cg.shared.global [%0], [%1], 16;\n" ::           \
                             "r"(sb), "l"(gb));                                         \
            }                                                                           \
            asm volatile("cp.async.commit_group;\n");                                   \
        } while (0)

    LOAD_STAGE(0, 0);

    for (int kt = 0; kt < 8; ++kt) {
        if (kt < 7) {
            LOAD_STAGE((kt + 1) & 1, (kt + 1) * 32);
            asm volatile("cp.async.wait_group 1;\n");
        } else {
            asm volatile("cp.async.wait_group 0;\n");
        }
        __syncthreads();

        const unsigned aBase = ((kt & 1) ? sA1 : sA0) + aLaneOff + (unsigned)(warpM * 64 * 80);
        const unsigned bBase = ((kt & 1) ? sB1 : sB0) + bLaneOff + (unsigned)(warpN * 32 * 80);

        #pragma unroll
        for (int ks = 0; ks < 2; ++ks) {
            unsigned a[4][4], b[4][2];
            #pragma unroll
            for (int mt = 0; mt < 4; ++mt) {
                unsigned addr = aBase + (unsigned)(mt * 16 * 80 + ks * 32);
                asm volatile("ldmatrix.sync.aligned.m8n8.x4.shared.b16 {%0,%1,%2,%3}, [%4];\n"
                             : "=r"(a[mt][0]), "=r"(a[mt][1]), "=r"(a[mt][2]), "=r"(a[mt][3])
                             : "r"(addr));
            }
            #pragma unroll
            for (int nt2 = 0; nt2 < 2; ++nt2) {
                unsigned addr = bBase + (unsigned)(nt2 * 16 * 80 + ks * 32);
                asm volatile("ldmatrix.sync.aligned.m8n8.x4.shared.b16 {%0,%1,%2,%3}, [%4];\n"
                             : "=r"(b[nt2 * 2][0]), "=r"(b[nt2 * 2][1]),
                               "=r"(b[nt2 * 2 + 1][0]), "=r"(b[nt2 * 2 + 1][1])
                             : "r"(addr));
            }
            #pragma unroll
            for (int mt = 0; mt < 4; ++mt)
                #pragma unroll
                for (int nt = 0; nt < 4; ++nt)
                    asm volatile(
                        "mma.sync.aligned.m16n8k16.row.col.f32.bf16.bf16.f32 "
                        "{%0,%1,%2,%3}, {%4,%5,%6,%7}, {%8,%9}, {%0,%1,%2,%3};\n"
                        : "+f"(d[mt][nt][0]), "+f"(d[mt][nt][1]),
                          "+f"(d[mt][nt][2]), "+f"(d[mt][nt][3])
                        : "r"(a[mt][0]), "r"(a[mt][1]), "r"(a[mt][2]), "r"(a[mt][3]),
                          "r"(b[nt][0]), "r"(b[nt][1]));
        }
        __syncthreads();
    }

    // epilogue: exp(10*d - 10); row sums always, column sums for off-diag tiles
    float cs_e[4], cs_o[4];
    #pragma unroll
    for (int nt = 0; nt < 4; ++nt) { cs_e[nt] = 0.0f; cs_o[nt] = 0.0f; }

    #pragma unroll
    for (int mt = 0; mt < 4; ++mt) {
        float s1 = 0.0f, s2 = 0.0f;
        #pragma unroll
        for (int nt = 0; nt < 4; ++nt) {
            float e0 = fast_ex2(fmaf(d[mt][nt][0], LOG2E10, -LOG2E10));
            float e1 = fast_ex2(fmaf(d[mt][nt][1], LOG2E10, -LOG2E10));
            float e2 = fast_ex2(fmaf(d[mt][nt][2], LOG2E10, -LOG2E10));
            float e3 = fast_ex2(fmaf(d[mt][nt][3], LOG2E10, -LOG2E10));
            s1 += e0 + e1;
            s2 += e2 + e3;
            cs_e[nt] += e0 + e2;     // col 2*tig
            cs_o[nt] += e1 + e3;     // col 2*tig+1
        }
        s1 += __shfl_xor_sync(0xffffffffu, s1, 1);
        s1 += __shfl_xor_sync(0xffffffffu, s1, 2);
        s2 += __shfl_xor_sync(0xffffffffu, s2, 1);
        s2 += __shfl_xor_sync(0xffffffffu, s2, 2);
        if (tig == 0) {
            atomicAdd(&s_rowsum[warpM * 64 + mt * 16 + gid],     s1);
            atomicAdd(&s_rowsum[warpM * 64 + mt * 16 + gid + 8], s2);
        }
    }
    if (!diag) {
        #pragma unroll
        for (int nt = 0; nt < 4; ++nt) {
            #pragma unroll
            for (int o = 4; o <= 16; o <<= 1) {
                cs_e[nt] += __shfl_xor_sync(0xffffffffu, cs_e[nt], o);
                cs_o[nt] += __shfl_xor_sync(0xffffffffu, cs_o[nt], o);
            }
        }
        if (gid == 0) {
            #pragma unroll
            for (int nt = 0; nt < 4; ++nt) {
                atomicAdd(&s_colsum[warpN * 32 + nt * 8 + tig * 2],     cs_e[nt]);
                atomicAdd(&s_colsum[warpN * 32 + nt * 8 + tig * 2 + 1], cs_o[nt]);
            }
        }
    }
    __syncthreads();
    if (tid < 128) {
        g_rowsum[((size_t)v * NBLK + bn) * NROWS + bm * 128 + tid] = s_rowsum[tid];
        if (!diag)
            g_rowsum[((size_t)v * NBLK + bm) * NROWS + bn * 128 + tid] = s_colsum[tid];
    }
}

// ---------------- kernel 3a: per-row lse - pos, block partials -------------
__global__ void finalize_kernel() {
    int tid = threadIdx.x;
    int gid = blockIdx.x * 256 + tid;         // 0..8191
    int v = gid >> 12;
    int i = gid & (NROWS - 1);

    float s = 0.0f;
    #pragma unroll
    for (int b = 0; b < NBLK; ++b)
        s += g_rowsum[((size_t)v * NBLK + b) * NROWS + i];

    float p10 = 10.0f * g_pos[i];
    float A = s - 1.0f + __expf(p10 - 10.0f);
    float term = 10.0f + logf(A) - p10;       // lse - pos

    __shared__ float red[256];
    red[tid] = term;
    __syncthreads();
    #pragma unroll
    for (int o = 128; o; o >>= 1) {
        if (tid < o) red[tid] += red[tid + o];
        __syncthreads();
    }
    if (tid == 0) g_blocksum[blockIdx.x] = red[0];
}

// ---------------- kernel 3b: final scalar ----------------------------------
__global__ void finalize2_kernel(float* __restrict__ out) {
    int lane = threadIdx.x;
    float s = g_blocksum[lane];
    #pragma unroll
    for (int o = 16; o; o >>= 1) s += __shfl_xor_sync(0xffffffffu, s, o);
    if (lane == 0) out[0] = s / 8192.0f;
}

// ---------------- launch ---------------------------------------------------
extern "C" void kernel_launch(void* const* d_in, const int* in_sizes, int n_in,
                              void* d_out, int out_size) {
    const float* zi = (const float*)d_in[0];   // z_i
    const float* zj = (const float*)d_in[1];   // z_j

    normalize_kernel<<<NROWS / 8, 256>>>(zi, zj);
    gram_kernel<<<dim3(NTRI, 2), 256>>>();
    finalize_kernel<<<32, 256>>>();
    finalize2_kernel<<<1, 32>>>((float*)d_out);
}

// round 7
// speedup vs baseline: 1.7803x; 1.0384x over previous
#include <cuda_runtime.h>
#include <cuda_bf16.h>
#include <cstdint>

// Problem constants
#define NROWS 4096
#define DIM   256
#define NBLK  32            // 4096 / 128
#define NTRI  528           // NBLK*(NBLK+1)/2
#define LOG2E10 14.42695040888963f

// ---------------- device scratch (no allocations allowed) ----------------
__device__ __align__(16) __nv_bfloat16 g_Zn[2ull * NROWS * DIM]; // [view][row][dim]
__device__ float g_pos[NROWS];
__device__ float g_rowsum[2 * NBLK * NROWS];   // [view][colblock][row]
__device__ float g_blocksum[32];
__device__ int   g_ticket;

__device__ __forceinline__ float fast_ex2(float x) {
    float y;
    asm("ex2.approx.ftz.f32 %0, %1;" : "=f"(y) : "f"(x));
    return y;
}

// ---------------- kernel 1: normalize rows, compute pos --------------------
__global__ void normalize_kernel(const float* __restrict__ zi, const float* __restrict__ zj) {
    if (blockIdx.x == 0 && threadIdx.x == 0) g_ticket = 0;

    int warp = threadIdx.x >> 5;
    int lane = threadIdx.x & 31;
    int row  = blockIdx.x * 8 + warp;

    const float4* zi4 = reinterpret_cast<const float4*>(zi + (size_t)row * DIM);
    const float4* zj4 = reinterpret_cast<const float4*>(zj + (size_t)row * DIM);
    float4 a0 = zi4[lane * 2], a1 = zi4[lane * 2 + 1];
    float4 b0 = zj4[lane * 2], b1 = zj4[lane * 2 + 1];

    float si = a0.x*a0.x + a0.y*a0.y + a0.z*a0.z + a0.w*a0.w
             + a1.x*a1.x + a1.y*a1.y + a1.z*a1.z + a1.w*a1.w;
    float sj = b0.x*b0.x + b0.y*b0.y + b0.z*b0.z + b0.w*b0.w
             + b1.x*b1.x + b1.y*b1.y + b1.z*b1.z + b1.w*b1.w;
    float dd = a0.x*b0.x + a0.y*b0.y + a0.z*b0.z + a0.w*b0.w
             + a1.x*b1.x + a1.y*b1.y + a1.z*b1.z + a1.w*b1.w;

    #pragma unroll
    for (int o = 16; o; o >>= 1) {
        si += __shfl_xor_sync(0xffffffffu, si, o);
        sj += __shfl_xor_sync(0xffffffffu, sj, o);
        dd += __shfl_xor_sync(0xffffffffu, dd, o);
    }
    float rsI = rsqrtf(si);
    float rsJ = rsqrtf(sj);

    {
        __nv_bfloat162 p0 = __floats2bfloat162_rn(b0.x * rsJ, b0.y * rsJ);
        __nv_bfloat162 p1 = __floats2bfloat162_rn(b0.z * rsJ, b0.w * rsJ);
        __nv_bfloat162 p2 = __floats2bfloat162_rn(b1.x * rsJ, b1.y * rsJ);
        __nv_bfloat162 p3 = __floats2bfloat162_rn(b1.z * rsJ, b1.w * rsJ);
        uint4 u;
        u.x = *reinterpret_cast<unsigned*>(&p0);
        u.y = *reinterpret_cast<unsigned*>(&p1);
        u.z = *reinterpret_cast<unsigned*>(&p2);
        u.w = *reinterpret_cast<unsigned*>(&p3);
        reinterpret_cast<uint4*>(g_Zn)[((size_t)row * DIM + lane * 8) / 8] = u;
    }
    {
        __nv_bfloat162 p0 = __floats2bfloat162_rn(a0.x * rsI, a0.y * rsI);
        __nv_bfloat162 p1 = __floats2bfloat162_rn(a0.z * rsI, a0.w * rsI);
        __nv_bfloat162 p2 = __floats2bfloat162_rn(a1.x * rsI, a1.y * rsI);
        __nv_bfloat162 p3 = __floats2bfloat162_rn(a1.z * rsI, a1.w * rsI);
        uint4 u;
        u.x = *reinterpret_cast<unsigned*>(&p0);
        u.y = *reinterpret_cast<unsigned*>(&p1);
        u.z = *reinterpret_cast<unsigned*>(&p2);
        u.w = *reinterpret_cast<unsigned*>(&p3);
        reinterpret_cast<uint4*>(g_Zn)[((size_t)NROWS * DIM + (size_t)row * DIM + lane * 8) / 8] = u;
    }
    if (lane == 0) g_pos[row] = dd * rsI * rsJ;
}

// ---------------- kernel 2: triangular Gram, 3-stage pipeline --------------
// Upper-triangular 128x128 tiles (bm<=bn) per view; off-diagonal tiles also
// emit column sums (row sums of the mirrored tile). bf16 mma.sync m16n8k16,
// ldmatrix fragment loads, 3-stage cp.async pipeline with ONE sync per step.
__global__ __launch_bounds__(256, 2) void gram_kernel() {
    const int v = blockIdx.y;

    int t = blockIdx.x, bm = 0, rem = NBLK;
    while (t >= rem) { t -= rem; ++bm; --rem; }
    const int bn = bm + t;
    const bool diag = (bm == bn);

    __shared__ __align__(16) __nv_bfloat16 As[3][128 * 40];
    __shared__ __align__(16) __nv_bfloat16 Bs[3][128 * 40];
    __shared__ float s_rowsum[128];
    __shared__ float s_colsum[128];

    const int tid  = threadIdx.x;
    const int lane = tid & 31;
    const int w    = tid >> 5;
    const int warpM = w >> 2;        // 0..1
    const int warpN = w & 3;         // 0..3
    const int gid  = lane >> 2;      // 0..7
    const int tig  = lane & 3;       // 0..3

    if (tid < 128) { s_rowsum[tid] = 0.0f; s_colsum[tid] = 0.0f; }

    const __nv_bfloat16* Zv = g_Zn + (size_t)v * NROWS * DIM;
    const __nv_bfloat16* Ag = Zv + (size_t)bm * 128 * DIM;
    const __nv_bfloat16* Bg = Zv + (size_t)bn * 128 * DIM;

    float d[4][4][4];
    #pragma unroll
    for (int mt = 0; mt < 4; ++mt)
        #pragma unroll
        for (int nt = 0; nt < 4; ++nt)
            #pragma unroll
            for (int x = 0; x < 4; ++x) d[mt][nt][x] = 0.0f;

    // per-lane ldmatrix base offsets (bytes), 40-bf16 (80B) row stride
    const unsigned aLaneOff = (unsigned)(((lane & 15) * 40 + (lane >> 4) * 8) * 2);
    const unsigned bLaneOff = (unsigned)(((((lane >> 4) * 8) + (lane & 7)) * 40 + ((lane >> 3) & 1) * 8) * 2);
    unsigned sAb[3], sBb[3];
    #pragma unroll
    for (int s = 0; s < 3; ++s) {
        sAb[s] = (unsigned)__cvta_generic_to_shared(&As[s][0]) + aLaneOff + (unsigned)(warpM * 64 * 80);
        sBb[s] = (unsigned)__cvta_generic_to_shared(&Bs[s][0]) + bLaneOff + (unsigned)(warpN * 32 * 80);
    }

    #define LOAD_STAGE(buf, k0)                                                         \
        do {                                                                            \
            _Pragma("unroll")                                                           \
            for (int p = 0; p < 2; ++p) {                                               \
                int c  = tid + p * 256;                                                 \
                int r  = c >> 2;                                                        \
                int cp = c & 3;                                                         \
                const void* ga = Ag + r * DIM + (k0) + cp * 8;                          \
                unsigned sa = (unsigned)__cvta_generic_to_shared(&As[buf][r * 40 + cp * 8]); \
                asm volatile("cp.async.cg.shared.global [%0], [%1], 16;\n" ::           \
                             "r"(sa), "l"(ga));                                         \
                const void* gb = Bg + r * DIM + (k0) + cp * 8;                          \
                unsigned sb = (unsigned)__cvta_generic_to_shared(&Bs[buf][r * 40 + cp * 8]); \
                asm volatile("cp.async.cg.shared.global [%0], [%1], 16;\n" ::           \
                             "r"(sb), "l"(gb));                                         \
            }                                                                           \
            asm volatile("cp.async.commit_group;\n");                                   \
        } while (0)

    LOAD_STAGE(0, 0);

    int buf = 0;
    #pragma unroll
    for (int kt = 0; kt < 8; ++kt) {
        if (kt < 7) {
            int nb = buf + 1; if (nb == 3) nb = 0;
            LOAD_STAGE(nb, (kt + 1) * 32);
            asm volatile("cp.async.wait_group 1;\n");
        } else {
            asm volatile("cp.async.wait_group 0;\n");
        }
        __syncthreads();   // single sync: stage `buf` ready; all warps past stage buf-2

        const unsigned aBase = sAb[buf];
        const unsigned bBase = sBb[buf];

        #pragma unroll
        for (int ks = 0; ks < 2; ++ks) {
            unsigned a[4][4], b[4][2];
            #pragma unroll
            for (int mt = 0; mt < 4; ++mt) {
                unsigned addr = aBase + (unsigned)(mt * 16 * 80 + ks * 32);
                asm volatile("ldmatrix.sync.aligned.m8n8.x4.shared.b16 {%0,%1,%2,%3}, [%4];\n"
                             : "=r"(a[mt][0]), "=r"(a[mt][1]), "=r"(a[mt][2]), "=r"(a[mt][3])
                             : "r"(addr));
            }
            #pragma unroll
            for (int nt2 = 0; nt2 < 2; ++nt2) {
                unsigned addr = bBase + (unsigned)(nt2 * 16 * 80 + ks * 32);
                asm volatile("ldmatrix.sync.aligned.m8n8.x4.shared.b16 {%0,%1,%2,%3}, [%4];\n"
                             : "=r"(b[nt2 * 2][0]), "=r"(b[nt2 * 2][1]),
                               "=r"(b[nt2 * 2 + 1][0]), "=r"(b[nt2 * 2 + 1][1])
                             : "r"(addr));
            }
            #pragma unroll
            for (int mt = 0; mt < 4; ++mt)
                #pragma unroll
                for (int nt = 0; nt < 4; ++nt)
                    asm volatile(
                        "mma.sync.aligned.m16n8k16.row.col.f32.bf16.bf16.f32 "
                        "{%0,%1,%2,%3}, {%4,%5,%6,%7}, {%8,%9}, {%0,%1,%2,%3};\n"
                        : "+f"(d[mt][nt][0]), "+f"(d[mt][nt][1]),
                          "+f"(d[mt][nt][2]), "+f"(d[mt][nt][3])
                        : "r"(a[mt][0]), "r"(a[mt][1]), "r"(a[mt][2]), "r"(a[mt][3]),
                          "r"(b[nt][0]), "r"(b[nt][1]));
        }
        ++buf; if (buf == 3) buf = 0;
    }

    // epilogue: exp(10*d - 10); row sums always, col sums for off-diag tiles
    float cs_e[4], cs_o[4];
    #pragma unroll
    for (int nt = 0; nt < 4; ++nt) { cs_e[nt] = 0.0f; cs_o[nt] = 0.0f; }

    #pragma unroll
    for (int mt = 0; mt < 4; ++mt) {
        float s1 = 0.0f, s2 = 0.0f;
        #pragma unroll
        for (int nt = 0; nt < 4; ++nt) {
            float e0 = fast_ex2(fmaf(d[mt][nt][0], LOG2E10, -LOG2E10));
            float e1 = fast_ex2(fmaf(d[mt][nt][1], LOG2E10, -LOG2E10));
            float e2 = fast_ex2(fmaf(d[mt][nt][2], LOG2E10, -LOG2E10));
            float e3 = fast_ex2(fmaf(d[mt][nt][3], LOG2E10, -LOG2E10));
            s1 += e0 + e1;
            s2 += e2 + e3;
            cs_e[nt] += e0 + e2;     // col 2*tig
            cs_o[nt] += e1 + e3;     // col 2*tig+1
        }
        s1 += __shfl_xor_sync(0xffffffffu, s1, 1);
        s1 += __shfl_xor_sync(0xffffffffu, s1, 2);
        s2 += __shfl_xor_sync(0xffffffffu, s2, 1);
        s2 += __shfl_xor_sync(0xffffffffu, s2, 2);
        if (tig == 0) {
            atomicAdd(&s_rowsum[warpM * 64 + mt * 16 + gid],     s1);
            atomicAdd(&s_rowsum[warpM * 64 + mt * 16 + gid + 8], s2);
        }
    }
    if (!diag) {
        #pragma unroll
        for (int nt = 0; nt < 4; ++nt) {
            #pragma unroll
            for (int o = 4; o <= 16; o <<= 1) {
                cs_e[nt] += __shfl_xor_sync(0xffffffffu, cs_e[nt], o);
                cs_o[nt] += __shfl_xor_sync(0xffffffffu, cs_o[nt], o);
            }
        }
        if (gid == 0) {
            #pragma unroll
            for (int nt = 0; nt < 4; ++nt) {
                atomicAdd(&s_colsum[warpN * 32 + nt * 8 + tig * 2],     cs_e[nt]);
                atomicAdd(&s_colsum[warpN * 32 + nt * 8 + tig * 2 + 1], cs_o[nt]);
            }
        }
    }
    __syncthreads();
    if (tid < 128) {
        g_rowsum[((size_t)v * NBLK + bn) * NROWS + bm * 128 + tid] = s_rowsum[tid];
        if (!diag)
            g_rowsum[((size_t)v * NBLK + bm) * NROWS + bn * 128 + tid] = s_colsum[tid];
    }
}

// ---------------- kernel 3: merged finalize (ticket) -----------------------
__global__ void finalize_kernel(float* __restrict__ out) {
    int tid = threadIdx.x;
    int gid = blockIdx.x * 256 + tid;         // 0..8191
    int v = gid >> 12;
    int i = gid & (NROWS - 1);

    float s = 0.0f;
    #pragma unroll
    for (int b = 0; b < NBLK; ++b)
        s += g_rowsum[((size_t)v * NBLK + b) * NROWS + i];

    float p10 = 10.0f * g_pos[i];
    float A = s - 1.0f + __expf(p10 - 10.0f);  // drop self term, add positive
    float term = 10.0f + logf(A) - p10;        // lse - pos

    __shared__ float red[256];
    red[tid] = term;
    __syncthreads();
    #pragma unroll
    for (int o = 128; o; o >>= 1) {
        if (tid < o) red[tid] += red[tid + o];
        __syncthreads();
    }
    if (tid == 0) {
        g_blocksum[blockIdx.x] = red[0];
        __threadfence();
        int tk = atomicAdd(&g_ticket, 1);
        if (tk == 31) {
            __threadfence();
            float tot = 0.0f;
            #pragma unroll
            for (int b = 0; b < 32; ++b) tot += g_blocksum[b];
            out[0] = tot / 8192.0f;
        }
    }
}

// ---------------- launch ---------------------------------------------------
extern "C" void kernel_launch(void* const* d_in, const int* in_sizes, int n_in,
                              void* d_out, int out_size) {
    const float* zi = (const float*)d_in[0];   // z_i
    const float* zj = (const float*)d_in[1];   // z_j

    normalize_kernel<<<NROWS / 8, 256>>>(zi, zj);
    gram_kernel<<<dim3(NTRI, 2), 256>>>();
    finalize_kernel<<<32, 256>>>((float*)d_out);
}

// round 9
// speedup vs baseline: 1.8473x; 1.0376x over previous
#include <cuda_runtime.h>
#include <cuda_fp16.h>
#include <cstdint>

// Problem constants
#define NROWS 4096
#define DIM   256
#define NBLK  32            // 4096 / 128
#define NTRI  528           // NBLK*(NBLK+1)/2
#define LOG2E10 14.42695040888963f

// ---------------- device scratch (no allocations allowed) ----------------
__device__ __align__(16) __half g_Zn[2ull * NROWS * DIM]; // [view][row][dim], fp16
__device__ float g_pos[NROWS];
__device__ float g_rowsum[2 * NBLK * NROWS];   // [view][colblock][row]
__device__ float g_blocksum[32];
__device__ int   g_ticket;

__device__ __forceinline__ float fast_ex2(float x) {
    float y;
    asm("ex2.approx.ftz.f32 %0, %1;" : "=f"(y) : "f"(x));
    return y;
}

// ---------------- kernel 1: normalize rows, compute pos --------------------
// One warp per row; 4-warp blocks for fine-grained wave scheduling.
__global__ void normalize_kernel(const float* __restrict__ zi, const float* __restrict__ zj) {
    if (blockIdx.x == 0 && threadIdx.x == 0) g_ticket = 0;

    int warp = threadIdx.x >> 5;
    int lane = threadIdx.x & 31;
    int row  = blockIdx.x * 4 + warp;

    const float4* zi4 = reinterpret_cast<const float4*>(zi + (size_t)row * DIM);
    const float4* zj4 = reinterpret_cast<const float4*>(zj + (size_t)row * DIM);
    float4 a0 = zi4[lane * 2], a1 = zi4[lane * 2 + 1];
    float4 b0 = zj4[lane * 2], b1 = zj4[lane * 2 + 1];

    float si = a0.x*a0.x + a0.y*a0.y + a0.z*a0.z + a0.w*a0.w
             + a1.x*a1.x + a1.y*a1.y + a1.z*a1.z + a1.w*a1.w;
    float sj = b0.x*b0.x + b0.y*b0.y + b0.z*b0.z + b0.w*b0.w
             + b1.x*b1.x + b1.y*b1.y + b1.z*b1.z + b1.w*b1.w;
    float dd = a0.x*b0.x + a0.y*b0.y + a0.z*b0.z + a0.w*b0.w
             + a1.x*b1.x + a1.y*b1.y + a1.z*b1.z + a1.w*b1.w;

    #pragma unroll
    for (int o = 16; o; o >>= 1) {
        si += __shfl_xor_sync(0xffffffffu, si, o);
        sj += __shfl_xor_sync(0xffffffffu, sj, o);
        dd += __shfl_xor_sync(0xffffffffu, dd, o);
    }
    float rsI = rsqrtf(si);
    float rsJ = rsqrtf(sj);

    {   // view 0 = z_j normalized (fp16)
        __half2 p0 = __floats2half2_rn(b0.x * rsJ, b0.y * rsJ);
        __half2 p1 = __floats2half2_rn(b0.z * rsJ, b0.w * rsJ);
        __half2 p2 = __floats2half2_rn(b1.x * rsJ, b1.y * rsJ);
        __half2 p3 = __floats2half2_rn(b1.z * rsJ, b1.w * rsJ);
        uint4 u;
        u.x = *reinterpret_cast<unsigned*>(&p0);
        u.y = *reinterpret_cast<unsigned*>(&p1);
        u.z = *reinterpret_cast<unsigned*>(&p2);
        u.w = *reinterpret_cast<unsigned*>(&p3);
        reinterpret_cast<uint4*>(g_Zn)[((size_t)row * DIM + lane * 8) / 8] = u;
    }
    {   // view 1 = z_i normalized (fp16)
        __half2 p0 = __floats2half2_rn(a0.x * rsI, a0.y * rsI);
        __half2 p1 = __floats2half2_rn(a0.z * rsI, a0.w * rsI);
        __half2 p2 = __floats2half2_rn(a1.x * rsI, a1.y * rsI);
        __half2 p3 = __floats2half2_rn(a1.z * rsI, a1.w * rsI);
        uint4 u;
        u.x = *reinterpret_cast<unsigned*>(&p0);
        u.y = *reinterpret_cast<unsigned*>(&p1);
        u.z = *reinterpret_cast<unsigned*>(&p2);
        u.w = *reinterpret_cast<unsigned*>(&p3);
        reinterpret_cast<uint4*>(g_Zn)[((size_t)NROWS * DIM + (size_t)row * DIM + lane * 8) / 8] = u;
    }
    if (lane == 0) g_pos[row] = dd * rsI * rsJ;
}

// ---------------- kernel 2: triangular Gram, f16-accum mma -----------------
// Upper-triangular 128x128 tiles (bm<=bn) per view; off-diagonal tiles also
// emit column sums (row sums of the mirrored tile). fp16 mma.sync m16n8k16
// with f16 accumulators (tests 2x-rate hypothesis; halves accum registers).
// ldmatrix fragment loads; 3-stage cp.async pipeline, one sync per k-step.
__global__ __launch_bounds__(256, 2) void gram_kernel() {
    const int v = blockIdx.y;

    int t = blockIdx.x, bm = 0, rem = NBLK;
    while (t >= rem) { t -= rem; ++bm; --rem; }
    const int bn = bm + t;
    const bool diag = (bm == bn);

    __shared__ __align__(16) __half As[3][128 * 40];
    __shared__ __align__(16) __half Bs[3][128 * 40];
    __shared__ float s_rowsum[128];
    __shared__ float s_colsum[128];

    const int tid  = threadIdx.x;
    const int lane = tid & 31;
    const int w    = tid >> 5;
    const int warpM = w >> 2;        // 0..1
    const int warpN = w & 3;         // 0..3
    const int gid  = lane >> 2;      // 0..7
    const int tig  = lane & 3;       // 0..3

    if (tid < 128) { s_rowsum[tid] = 0.0f; s_colsum[tid] = 0.0f; }

    const __half* Zv = g_Zn + (size_t)v * NROWS * DIM;
    const __half* Ag = Zv + (size_t)bm * 128 * DIM;
    const __half* Bg = Zv + (size_t)bn * 128 * DIM;

    // f16 accumulators: 2 regs per fragment (4 halfs)
    unsigned d16[4][4][2];
    #pragma unroll
    for (int mt = 0; mt < 4; ++mt)
        #pragma unroll
        for (int nt = 0; nt < 4; ++nt) { d16[mt][nt][0] = 0u; d16[mt][nt][1] = 0u; }

    // per-lane ldmatrix base offsets (bytes), 40-half (80B) row stride
    const unsigned aLaneOff = (unsigned)(((lane & 15) * 40 + (lane >> 4) * 8) * 2);
    const unsigned bLaneOff = (unsigned)(((((lane >> 4) * 8) + (lane & 7)) * 40 + ((lane >> 3) & 1) * 8) * 2);
    unsigned sAb[3], sBb[3];
    #pragma unroll
    for (int s = 0; s < 3; ++s) {
        sAb[s] = (unsigned)__cvta_generic_to_shared(&As[s][0]) + aLaneOff + (unsigned)(warpM * 64 * 80);
        sBb[s] = (unsigned)__cvta_generic_to_shared(&Bs[s][0]) + bLaneOff + (unsigned)(warpN * 32 * 80);
    }

    #define LOAD_STAGE(buf, k0)                                                         \
        do {                                                                            \
            _Pragma("unroll")                                                           \
            for (int p = 0; p < 2; ++p) {                                               \
                int c  = tid + p * 256;                                                 \
                int r  = c >> 2;                                                        \
                int cp = c & 3;                                                         \
                const void* ga = Ag + r * DIM + (k0) + cp * 8;                          \
                unsigned sa = (unsigned)__cvta_generic_to_shared(&As[buf][r * 40 + cp * 8]); \
                asm volatile("cp.async.cg.shared.global [%0], [%1], 16;\n" ::           \
                             "r"(sa), "l"(ga));                                         \
                const void* gb = Bg + r * DIM + (k0) + cp * 8;                          \
                unsigned sb = (unsigned)__cvta_generic_to_shared(&Bs[buf][r * 40 + cp * 8]); \
                asm volatile("cp.async.cg.shared.global [%0], [%1], 16;\n" ::           \
                             "r"(sb), "l"(gb));                                         \
            }                                                                           \
            asm volatile("cp.async.commit_group;\n");                                   \
        } while (0)

    LOAD_STAGE(0, 0);

    int buf = 0;
    #pragma unroll
    for (int kt = 0; kt < 8; ++kt) {
        if (kt < 7) {
            int nb = buf + 1; if (nb == 3) nb = 0;
            LOAD_STAGE(nb, (kt + 1) * 32);
            asm volatile("cp.async.wait_group 1;\n");
        } else {
            asm volatile("cp.async.wait_group 0;\n");
        }
        __syncthreads();   // stage `buf` ready; all warps past stage buf-2

        const unsigned aBase = sAb[buf];
        const unsigned bBase = sBb[buf];

        #pragma unroll
        for (int ks = 0; ks < 2; ++ks) {
            unsigned a[4][4], b[4][2];
            #pragma unroll
            for (int mt = 0; mt < 4; ++mt) {
                unsigned addr = aBase + (unsigned)(mt * 16 * 80 + ks * 32);
                asm volatile("ldmatrix.sync.aligned.m8n8.x4.shared.b16 {%0,%1,%2,%3}, [%4];\n"
                             : "=r"(a[mt][0]), "=r"(a[mt][1]), "=r"(a[mt][2]), "=r"(a[mt][3])
                             : "r"(addr));
            }
            #pragma unroll
            for (int nt2 = 0; nt2 < 2; ++nt2) {
                unsigned addr = bBase + (unsigned)(nt2 * 16 * 80 + ks * 32);
                asm volatile("ldmatrix.sync.aligned.m8n8.x4.shared.b16 {%0,%1,%2,%3}, [%4];\n"
                             : "=r"(b[nt2 * 2][0]), "=r"(b[nt2 * 2][1]),
                               "=r"(b[nt2 * 2 + 1][0]), "=r"(b[nt2 * 2 + 1][1])
                             : "r"(addr));
            }
            #pragma unroll
            for (int mt = 0; mt < 4; ++mt)
                #pragma unroll
                for (int nt = 0; nt < 4; ++nt)
                    asm volatile(
                        "mma.sync.aligned.m16n8k16.row.col.f16.f16.f16.f16 "
                        "{%0,%1}, {%2,%3,%4,%5}, {%6,%7}, {%0,%1};\n"
                        : "+r"(d16[mt][nt][0]), "+r"(d16[mt][nt][1])
                        : "r"(a[mt][0]), "r"(a[mt][1]), "r"(a[mt][2]), "r"(a[mt][3]),
                          "r"(b[nt][0]), "r"(b[nt][1]));
        }
        ++buf; if (buf == 3) buf = 0;
    }

    // epilogue: unpack f16 accums, exp(10*d - 10); row sums always,
    // col sums for off-diag tiles (mirrored row sums).
    float cs_e[4], cs_o[4];
    #pragma unroll
    for (int nt = 0; nt < 4; ++nt) { cs_e[nt] = 0.0f; cs_o[nt] = 0.0f; }

    #pragma unroll
    for (int mt = 0; mt < 4; ++mt) {
        float s1 = 0.0f, s2 = 0.0f;
        #pragma unroll
        for (int nt = 0; nt < 4; ++nt) {
            float2 lo = __half22float2(*reinterpret_cast<__half2*>(&d16[mt][nt][0]));
            float2 hi = __half22float2(*reinterpret_cast<__half2*>(&d16[mt][nt][1]));
            float e0 = fast_ex2(fmaf(lo.x, LOG2E10, -LOG2E10));
            float e1 = fast_ex2(fmaf(lo.y, LOG2E10, -LOG2E10));
            float e2 = fast_ex2(fmaf(hi.x, LOG2E10, -LOG2E10));
            float e3 = fast_ex2(fmaf(hi.y, LOG2E10, -LOG2E10));
            s1 += e0 + e1;
            s2 += e2 + e3;
            cs_e[nt] += e0 + e2;     // col 2*tig
            cs_o[nt] += e1 + e3;     // col 2*tig+1
        }
        s1 += __shfl_xor_sync(0xffffffffu, s1, 1);
        s1 += __shfl_xor_sync(0xffffffffu, s1, 2);
        s2 += __shfl_xor_sync(0xffffffffu, s2, 1);
        s2 += __shfl_xor_sync(0xffffffffu, s2, 2);
        if (tig == 0) {
            atomicAdd(&s_rowsum[warpM * 64 + mt * 16 + gid],     s1);
            atomicAdd(&s_rowsum[warpM * 64 + mt * 16 + gid + 8], s2);
        }
    }
    if (!diag) {
        #pragma unroll
        for (int nt = 0; nt < 4; ++nt) {
            #pragma unroll
            for (int o = 4; o <= 16; o <<= 1) {
                cs_e[nt] += __shfl_xor_sync(0xffffffffu, cs_e[nt], o);
                cs_o[nt] += __shfl_xor_sync(0xffffffffu, cs_o[nt], o);
            }
        }
        if (gid == 0) {
            #pragma unroll
            for (int nt = 0; nt < 4; ++nt) {
                atomicAdd(&s_colsum[warpN * 32 + nt * 8 + tig * 2],     cs_e[nt]);
                atomicAdd(&s_colsum[warpN * 32 + nt * 8 + tig * 2 + 1], cs_o[nt]);
            }
        }
    }
    __syncthreads();
    if (tid < 128) {
        g_rowsum[((size_t)v * NBLK + bn) * NROWS + bm * 128 + tid] = s_rowsum[tid];
        if (!diag)
            g_rowsum[((size_t)v * NBLK + bm) * NROWS + bn * 128 + tid] = s_colsum[tid];
    }
}

// ---------------- kernel 3: merged finalize (ticket) -----------------------
__global__ void finalize_kernel(float* __restrict__ out) {
    int tid = threadIdx.x;
    int gid = blockIdx.x * 256 + tid;         // 0..8191
    int v = gid >> 12;
    int i = gid & (NROWS - 1);

    float s = 0.0f;
    #pragma unroll
    for (int b = 0; b < NBLK; ++b)
        s += g_rowsum[((size_t)v * NBLK + b) * NROWS + i];

    float p10 = 10.0f * g_pos[i];
    float A = s - 1.0f + __expf(p10 - 10.0f);  // drop self term, add positive
    float term = 10.0f + logf(A) - p10;        // lse - pos

    __shared__ float red[256];
    red[tid] = term;
    __syncthreads();
    #pragma unroll
    for (int o = 128; o; o >>= 1) {
        if (tid < o) red[tid] += red[tid + o];
        __syncthreads();
    }
    if (tid == 0) {
        g_blocksum[blockIdx.x] = red[0];
        __threadfence();
        int tk = atomicAdd(&g_ticket, 1);
        if (tk == 31) {
            __threadfence();
            float tot = 0.0f;
            #pragma unroll
            for (int b = 0; b < 32; ++b) tot += g_blocksum[b];
            out[0] = tot / 8192.0f;
        }
    }
}

// ---------------- launch ---------------------------------------------------
extern "C" void kernel_launch(void* const* d_in, const int* in_sizes, int n_in,
                              void* d_out, int out_size) {
    const float* zi = (const float*)d_in[0];   // z_i
    const float* zj = (const float*)d_in[1];   // z_j

    normalize_kernel<<<NROWS / 4, 128>>>(zi, zj);
    gram_kernel<<<dim3(NTRI, 2), 256>>>();
    finalize_kernel<<<32, 256>>>((float*)d_out);
}